// round 1
// baseline (speedup 1.0000x reference)
#include <cuda_runtime.h>
#include <math.h>

#define BDIM 256
#define NPTS 64
#define EPS_CASE 1e-4f

__global__ __launch_bounds__(BDIM)
void scatter_polygon_kernel(const float* __restrict__ points,
                            const float* __restrict__ phi,
                            float* __restrict__ out,
                            int B, int N) {
    __shared__ float2 sp[NPTS];

    const int b = blockIdx.y;
    const int n = blockIdx.x * BDIM + threadIdx.x;

    // Stage points[b, :, :] (64 x float2 = 512B) into shared memory.
    if (threadIdx.x < 2 * NPTS) {
        reinterpret_cast<float*>(sp)[threadIdx.x] =
            points[b * 2 * NPTS + threadIdx.x];
    }
    __syncthreads();

    if (n >= N) return;

    // Per-angle constants.
    const float ph = phi[n];
    float sphi, cphi;
    sincosf(ph, &sphi, &cphi);
    const float qx = cphi;
    const float qy = sphi - 1.0f;
    // cross = [[0,-1],[1,0]]; q_cross = cross @ q = (-qy, qx)
    const float qcx = -qy;
    const float qcy = qx;
    const float scale = 1.0f / fabsf(qx * qx + qy * qy);

    // Edge k: p0 = points[k-1] (wrap), p1 = points[k].
    // e^{i p.q} is shared between consecutive edges -> one sincos per point.
    float2 pprev = sp[NPTS - 1];
    float dprev = pprev.x * qx + pprev.y * qy;
    float sprev, cprev;
    sincosf(dprev, &sprev, &cprev);

    float sum_r = 0.0f;
    float sum_i = 0.0f;

#pragma unroll 4
    for (int k = 0; k < NPTS; ++k) {
        const float2 pc = sp[k];
        const float dcur = pc.x * qx + pc.y * qy;
        float sc, cc;
        sincosf(dcur, &sc, &cc);

        const float dx = pc.x - pprev.x;
        const float dy = pc.y - pprev.y;
        const float ddq  = dx * qx  + dy * qy;   // matches reference d.q
        const float ddqc = dx * qcx + dy * qcy;  // d . q_cross

        float rr, ri;
        if (fabsf(ddq) >= EPS_CASE) {
            // f_p = -e^{i d};  f1 - f0 = (cprev - cc) + i (sprev - sc)
            const float inv = 1.0f / ddq;
            const float g = ddqc * inv;
            rr = g * (cprev - cc);
            ri = g * (sprev - sc);
        } else {
            // case2 = ddqc * (-i) * e^{i dprev} = ddqc*(sprev - i*cprev)
            rr =  ddqc * sprev;
            ri = -ddqc * cprev;
        }
        sum_r += rr;
        sum_i += ri;

        pprev = pc;
        dprev = dcur;
        sprev = sc;
        cprev = cc;
    }

    out[(b * 2 + 0) * N + n] = scale * sum_r;
    out[(b * 2 + 1) * N + n] = scale * sum_i;
}

extern "C" void kernel_launch(void* const* d_in, const int* in_sizes, int n_in,
                              void* d_out, int out_size) {
    const float* points = (const float*)d_in[0];  // [B, 64, 2] f32
    const float* phi    = (const float*)d_in[1];  // [N] f32
    float* out = (float*)d_out;                   // [B, 2, N] f32

    const int N = in_sizes[1];
    const int B = in_sizes[0] / (2 * NPTS);

    dim3 grid((N + BDIM - 1) / BDIM, B);
    scatter_polygon_kernel<<<grid, BDIM>>>(points, phi, out, B, N);
}

// round 3
// speedup vs baseline: 1.2230x; 1.2230x over previous
#include <cuda_runtime.h>
#include <math.h>

#define BDIM 128
#define NPTS 64
#define EPS_CASE 1e-4f

__device__ __forceinline__ float rcp_approx(float x) {
    float r;
    asm("rcp.approx.f32 %0, %1;" : "=f"(r) : "f"(x));
    return r;
}

// Fast sincos for |x| <~ 100. Cody-Waite mod-pi/2 + cephes polys.
// Abs error ~1e-8; relative accuracy preserved for small |x| (no MUFU floor).
__device__ __forceinline__ void fast_sincos(float x, float* s_out, float* c_out) {
    const float MAGIC = 12582912.0f;            // 1.5 * 2^23
    float t = fmaf(x, 0.63661975f, MAGIC);      // round(x * 2/pi) via magic add
    int   ni = __float_as_int(t);               // low bits = n (two's complement)
    float nf = t - MAGIC;

    float r = fmaf(nf, -1.57079637e+00f, x);    // x - n*PIO2_HI
    r = fmaf(nf, 4.37113883e-08f, r);           // + n*(PIO2_HI - pi/2)

    float r2 = r * r;
    // sin poly on [-pi/4, pi/4]
    float ws = fmaf(r2, -1.95152959e-04f, 8.33216087e-03f);
    ws = fmaf(r2, ws, -1.66666546e-01f);
    float sp = fmaf(r * r2, ws, r);
    // cos poly on [-pi/4, pi/4]
    float wc = fmaf(r2, 2.44331573e-05f, -1.38873163e-03f);
    wc = fmaf(r2, wc, 4.16666457e-02f);
    float cp = fmaf(r2 * r2, wc, fmaf(r2, -0.5f, 1.0f));

    // quadrant: n&1 swaps sin/cos; signs from bit1 of n and n+1.
    bool swap = (ni & 1) != 0;
    float s_ = swap ? cp : sp;
    float c_ = swap ? sp : cp;
    int sgn_s = (ni & 2) << 30;
    int sgn_c = ((ni + 1) & 2) << 30;
    *s_out = __int_as_float(__float_as_int(s_) ^ sgn_s);
    *c_out = __int_as_float(__float_as_int(c_) ^ sgn_c);
}

__global__ __launch_bounds__(BDIM)
void scatter_polygon_kernel(const float* __restrict__ points,
                            const float* __restrict__ phi,
                            float* __restrict__ out,
                            int B, int N) {
    __shared__ float2 spts[NPTS];

    const int b = blockIdx.y;
    const int n = blockIdx.x * BDIM + threadIdx.x;

    // Stage points[b] (64 x float2 = 512B): 128 threads load 128 floats.
    reinterpret_cast<float*>(spts)[threadIdx.x] = points[b * 2 * NPTS + threadIdx.x];
    __syncthreads();

    if (n >= N) return;

    // Per-angle constants (library sincos once per thread — negligible cost,
    // full accuracy for phi in [0, 2pi)).
    const float ph = phi[n];
    float sphi, cphi;
    sincosf(ph, &sphi, &cphi);
    const float qx = cphi;
    const float qy = sphi - 1.0f;
    // q_cross = cross @ q = (-qy, qx)
    const float scale = 1.0f / fabsf(qx * qx + qy * qy);

    // Edge k: p0 = points[k-1 mod P], p1 = points[k]; one sincos per point.
    float2 pp = spts[NPTS - 1];
    float dprev = fmaf(pp.x, qx, pp.y * qy);
    float sprev, cprev;
    fast_sincos(dprev, &sprev, &cprev);

    float sum_r = 0.0f;
    float sum_i = 0.0f;

#pragma unroll 8
    for (int k = 0; k < NPTS; ++k) {
        const float2 pc = spts[k];
        const float dcur = fmaf(pc.x, qx, pc.y * qy);
        float sc, cc;
        fast_sincos(dcur, &sc, &cc);

        const float dx = pc.x - pp.x;
        const float dy = pc.y - pp.y;
        const float ddq  = fmaf(dx, qx, dy * qy);            // d . q
        const float ddqc = fmaf(dy, qx, -(dx * qy));         // d . q_cross

        // case1: g*(f1-f0) with f_p = -e^{i d_p}; case2: ddqc*(-i)e^{i d0}
        const float inv = rcp_approx(ddq);
        const float g = ddqc * inv;
        const bool big = fabsf(ddq) >= EPS_CASE;
        const float rr = big ? g * (cprev - cc) :  ddqc * sprev;
        const float ri = big ? g * (sprev - sc) : -(ddqc * cprev);
        sum_r += rr;
        sum_i += ri;

        pp = pc;
        sprev = sc;
        cprev = cc;
    }

    out[(b * 2 + 0) * N + n] = scale * sum_r;
    out[(b * 2 + 1) * N + n] = scale * sum_i;
}

extern "C" void kernel_launch(void* const* d_in, const int* in_sizes, int n_in,
                              void* d_out, int out_size) {
    const float* points = (const float*)d_in[0];  // [B, 64, 2] f32
    const float* phi    = (const float*)d_in[1];  // [N] f32
    float* out = (float*)d_out;                   // [B, 2, N] f32

    const int N = in_sizes[1];
    const int B = in_sizes[0] / (2 * NPTS);

    dim3 grid((N + BDIM - 1) / BDIM, B);
    scatter_polygon_kernel<<<grid, BDIM>>>(points, phi, out, B, N);
}

// round 4
// speedup vs baseline: 1.2696x; 1.0380x over previous
#include <cuda_runtime.h>
#include <math.h>

#define BDIM 128
#define NPTS 64

#define PI_F     3.14159265358979f
#define INV_PI_F 0.318309886183791f
#define MAGIC_F  12582912.0f            // 1.5 * 2^23
#define EPS_U    3.18309886e-5f         // 1e-4 / pi (threshold in u-units)

__device__ __forceinline__ float rcp_approx(float x) {
    float r;
    asm("rcp.approx.f32 %0, %1;" : "=f"(r) : "f"(x));
    return r;
}

// Evaluate projections + sincos for one point.
// u  = (p.q)/pi, hc = (p.q_cross)/pi, (s,c) = sincos(p.q).
// mod-pi reduction: sin(d) = (-1)^n sin(r), cos(d) = (-1)^n cos(r),
// r in [-pi/2, pi/2]; Taylor deg-11/12 polys (abs err < 6e-8, rel-accurate
// for small args since leading coeffs are exact).
__device__ __forceinline__ void eval_point(float px, float py,
                                           float qxp, float qyp,
                                           float& u, float& hc,
                                           float& s, float& c) {
    u  = fmaf(px, qxp, py * qyp);
    hc = fmaf(py, qxp, -(px * qyp));

    const float t  = u + MAGIC_F;
    const int   ni = __float_as_int(t);
    const float nf = t - MAGIC_F;
    const float fr = u - nf;            // exact (Sterbenz)
    const float r  = fr * PI_F;
    const float r2 = r * r;

    float ws = fmaf(r2, -2.5052108e-8f, 2.7557319e-6f);
    ws = fmaf(r2, ws, -1.9841270e-4f);
    ws = fmaf(r2, ws, 8.3333333e-3f);
    ws = fmaf(r2, ws, -1.6666667e-1f);
    float sp = fmaf(r * r2, ws, r);

    float wc = fmaf(r2, 2.0876757e-9f, -2.7557319e-7f);
    wc = fmaf(r2, wc, 2.4801587e-5f);
    wc = fmaf(r2, wc, -1.3888889e-3f);
    wc = fmaf(r2, wc, 4.1666667e-2f);
    float cp = fmaf(r2 * r2, wc, fmaf(r2, -0.5f, 1.0f));

    const int sgn = ni << 31;           // parity of n -> sign bit
    s = __int_as_float(__float_as_int(sp) ^ sgn);
    c = __int_as_float(__float_as_int(cp) ^ sgn);
}

__global__ __launch_bounds__(BDIM)
void scatter_polygon_kernel(const float* __restrict__ points,
                            const float* __restrict__ phi,
                            float* __restrict__ out,
                            int B, int N) {
    __shared__ float2 spts[NPTS];

    const int b = blockIdx.y;
    const int n = blockIdx.x * BDIM + threadIdx.x;

    reinterpret_cast<float*>(spts)[threadIdx.x] = points[b * 2 * NPTS + threadIdx.x];
    __syncthreads();

    if (n >= N) return;

    const float ph = phi[n];
    float sphi, cphi;
    sincosf(ph, &sphi, &cphi);          // once per thread; accurate
    const float qx = cphi;
    const float qy = sphi - 1.0f;
    const float qxp = qx * INV_PI_F;    // fold 1/pi into the projections
    const float qyp = qy * INV_PI_F;
    const float scale = 1.0f / fabsf(qx * qx + qy * qy);

    // prev = point[NPTS-1] (edge k: p0 = point[k-1 mod P])
    float2 pp = spts[NPTS - 1];
    float uprev, hcprev, sprev, cprev;
    eval_point(pp.x, pp.y, qxp, qyp, uprev, hcprev, sprev, cprev);

    float sum_r = 0.0f;
    float sum_i = 0.0f;

#pragma unroll 8
    for (int k = 0; k < NPTS; ++k) {
        const float2 pc = spts[k];
        float uc, hcc, sc, cc;
        eval_point(pc.x, pc.y, qxp, qyp, uc, hcc, sc, cc);

        const float du = uc - uprev;        // ddq / pi
        const float dc = hcc - hcprev;      // ddqc / pi

        const float inv = rcp_approx(du);
        const float g = dc * inv;           // ddqc / ddq
        const bool big = fabsf(du) >= EPS_U;

        // case1: g * (f1 - f0), f_p = -e^{i d_p}
        const float rr1 = g * (cprev - cc);
        const float ri1 = g * (sprev - sc);
        // case2: ddqc * (-i) e^{i d0} = ddqc*(s0 - i c0), ddqc = pi*dc
        const float dq  = PI_F * dc;
        const float rr2 = dq * sprev;
        const float ri2 = -(dq * cprev);

        sum_r += big ? rr1 : rr2;
        sum_i += big ? ri1 : ri2;

        uprev = uc; hcprev = hcc; sprev = sc; cprev = cc;
    }

    out[(b * 2 + 0) * N + n] = scale * sum_r;
    out[(b * 2 + 1) * N + n] = scale * sum_i;
}

extern "C" void kernel_launch(void* const* d_in, const int* in_sizes, int n_in,
                              void* d_out, int out_size) {
    const float* points = (const float*)d_in[0];  // [B, 64, 2] f32
    const float* phi    = (const float*)d_in[1];  // [N] f32
    float* out = (float*)d_out;                   // [B, 2, N] f32

    const int N = in_sizes[1];
    const int B = in_sizes[0] / (2 * NPTS);

    dim3 grid((N + BDIM - 1) / BDIM, B);
    scatter_polygon_kernel<<<grid, BDIM>>>(points, phi, out, B, N);
}

// round 5
// speedup vs baseline: 1.3905x; 1.0952x over previous
#include <cuda_runtime.h>
#include <math.h>

typedef unsigned long long ull;

#define BDIM 128
#define NPTS 64
#define PI_F      3.14159265358979f
#define INV_PI_F  0.318309886183791f
#define MAGIC_F   12582912.0f
#define EPS_U     3.1830989e-5f   // 1e-4 / pi

__device__ __forceinline__ ull pack2(float lo, float hi) {
    ull r; asm("mov.b64 %0, {%1, %2};" : "=l"(r) : "f"(lo), "f"(hi)); return r;
}
__device__ __forceinline__ void unpack2(ull v, float& lo, float& hi) {
    asm("mov.b64 {%0, %1}, %2;" : "=f"(lo), "=f"(hi) : "l"(v));
}
__device__ __forceinline__ ull fma2(ull a, ull b, ull c) {
    ull d; asm("fma.rn.f32x2 %0, %1, %2, %3;" : "=l"(d) : "l"(a), "l"(b), "l"(c)); return d;
}
__device__ __forceinline__ ull mul2(ull a, ull b) {
    ull d; asm("mul.rn.f32x2 %0, %1, %2;" : "=l"(d) : "l"(a), "l"(b)); return d;
}
__device__ __forceinline__ ull add2(ull a, ull b) {
    ull d; asm("add.rn.f32x2 %0, %1, %2;" : "=l"(d) : "l"(a), "l"(b)); return d;
}
__device__ __forceinline__ float rcp_approx(float x) {
    float r; asm("rcp.approx.f32 %0, %1;" : "=f"(r) : "f"(x)); return r;
}
__device__ __forceinline__ float fneg_bits(float x) {
    return __int_as_float(__float_as_int(x) ^ 0x80000000);
}

__global__ __launch_bounds__(BDIM)
void scatter_polygon_kernel(const float* __restrict__ points,
                            const float* __restrict__ phi,
                            float* __restrict__ out,
                            int B, int N) {
    __shared__ float2 spts[NPTS];

    const int b = blockIdx.y;
    const int half = N >> 1;
    const int n0 = blockIdx.x * BDIM + threadIdx.x;
    const int n1 = n0 + half;

    reinterpret_cast<float*>(spts)[threadIdx.x] = points[b * 2 * NPTS + threadIdx.x];
    __syncthreads();

    if (n0 >= half) return;

    // Per-angle constants — accurate libm sincos (exact reduction matters near
    // phi = pi/2 where |q| -> 0 and scale blows up).
    float sA, cA, sB, cB;
    sincosf(phi[n0], &sA, &cA);
    sincosf(phi[n1], &sB, &cB);
    const float q0x = cA, q0y = sA - 1.0f;
    const float q1x = cB, q1y = sB - 1.0f;
    const float scale0 = 1.0f / fabsf(q0x * q0x + q0y * q0y);
    const float scale1 = 1.0f / fabsf(q1x * q1x + q1y * q1y);

    // Packed loop constants (1/pi folded into projection vectors).
    const ull QXP   = pack2(q0x * INV_PI_F,  q1x * INV_PI_F);
    const ull QYP   = pack2(q0y * INV_PI_F,  q1y * INV_PI_F);
    const ull NQYP  = pack2(-q0y * INV_PI_F, -q1y * INV_PI_F);
    const ull MAGIC2 = pack2(MAGIC_F, MAGIC_F);
    const ull M1     = pack2(-1.0f, -1.0f);
    const ull PIV    = pack2(PI_F, PI_F);
    const ull ONEV   = pack2(1.0f, 1.0f);
    const ull MHALF  = pack2(-0.5f, -0.5f);
    // sin Taylor (deg 11), cos Taylor (deg 12) — same coeffs as scalar kernel.
    const ull S11 = pack2(-2.5052108e-8f, -2.5052108e-8f);
    const ull S9  = pack2( 2.7557319e-6f,  2.7557319e-6f);
    const ull S7  = pack2(-1.9841270e-4f, -1.9841270e-4f);
    const ull S5  = pack2( 8.3333333e-3f,  8.3333333e-3f);
    const ull S3  = pack2(-1.6666667e-1f, -1.6666667e-1f);
    const ull D12 = pack2( 2.0876757e-9f,  2.0876757e-9f);
    const ull D10 = pack2(-2.7557319e-7f, -2.7557319e-7f);
    const ull D8  = pack2( 2.4801587e-5f,  2.4801587e-5f);
    const ull D6  = pack2(-1.3888889e-3f, -1.3888889e-3f);
    const ull D4  = pack2( 4.1666667e-2f,  4.1666667e-2f);

    // eval_pt: packed projections + mod-pi reduction + sincos for both lanes.
    auto eval_pt = [&](float px, float py,
                       float& u0, float& u1, float& hc0, float& hc1,
                       float& s0, float& s1, float& c0, float& c1) {
        const ull PX = pack2(px, px);
        const ull PY = pack2(py, py);
        const ull U  = fma2(PX, QXP, mul2(PY, QYP));    // (p.q)/pi per lane
        const ull HC = fma2(PX, NQYP, mul2(PY, QXP));   // (p.q_cross)/pi per lane
        const ull T  = add2(U, MAGIC2);
        const ull NF = fma2(MAGIC2, M1, T);             // round(u)
        const ull FR = fma2(NF, M1, U);                 // u - n (exact)
        const ull R  = mul2(FR, PIV);
        const ull R2 = mul2(R, R);
        const ull R3 = mul2(R2, R);
        ull W = fma2(R2, S11, S9);
        W = fma2(R2, W, S7);
        W = fma2(R2, W, S5);
        W = fma2(R2, W, S3);
        const ull SP = fma2(R3, W, R);
        ull V = fma2(R2, D12, D10);
        V = fma2(R2, V, D8);
        V = fma2(R2, V, D6);
        V = fma2(R2, V, D4);
        V = fma2(R2, V, MHALF);
        const ull CP = fma2(R2, V, ONEV);

        float t0f, t1f, sp0, sp1, cp0, cp1;
        unpack2(U, u0, u1);
        unpack2(HC, hc0, hc1);
        unpack2(T, t0f, t1f);
        unpack2(SP, sp0, sp1);
        unpack2(CP, cp0, cp1);
        const int sg0 = __float_as_int(t0f) << 31;   // (-1)^n sign bit
        const int sg1 = __float_as_int(t1f) << 31;
        s0 = __int_as_float(__float_as_int(sp0) ^ sg0);
        s1 = __int_as_float(__float_as_int(sp1) ^ sg1);
        c0 = __int_as_float(__float_as_int(cp0) ^ sg0);
        c1 = __int_as_float(__float_as_int(cp1) ^ sg1);
    };

    // Previous point = spts[NPTS-1] (edge k: p0 = point[k-1 mod P]).
    float up0, up1, hp0, hp1, sprev0, sprev1, cprev0, cprev1;
    {
        const float2 pl = spts[NPTS - 1];
        eval_pt(pl.x, pl.y, up0, up1, hp0, hp1, sprev0, sprev1, cprev0, cprev1);
    }

    float sum_r0 = 0.0f, sum_i0 = 0.0f, sum_r1 = 0.0f, sum_i1 = 0.0f;

#pragma unroll 4
    for (int k = 0; k < NPTS; ++k) {
        const float2 pc = spts[k];
        float u0, u1, hc0, hc1, s0, s1, c0, c1;
        eval_pt(pc.x, pc.y, u0, u1, hc0, hc1, s0, s1, c0, c1);

        // lane 0
        {
            const float du = u0 - up0;                 // ddq / pi
            const float dc = hc0 - hp0;                // ddqc / pi
            const float g  = dc * rcp_approx(du);      // ddqc / ddq
            const float dq = PI_F * dc;                // ddqc
            const bool big = fabsf(du) >= EPS_U;
            const float dS = sprev0 - s0;
            const float dC = cprev0 - c0;
            const float fr = big ? g : dq;
            const float fi = big ? g : fneg_bits(dq);
            const float vr = big ? dC : sprev0;
            const float vi = big ? dS : cprev0;
            sum_r0 = fmaf(fr, vr, sum_r0);
            sum_i0 = fmaf(fi, vi, sum_i0);
        }
        // lane 1
        {
            const float du = u1 - up1;
            const float dc = hc1 - hp1;
            const float g  = dc * rcp_approx(du);
            const float dq = PI_F * dc;
            const bool big = fabsf(du) >= EPS_U;
            const float dS = sprev1 - s1;
            const float dC = cprev1 - c1;
            const float fr = big ? g : dq;
            const float fi = big ? g : fneg_bits(dq);
            const float vr = big ? dC : sprev1;
            const float vi = big ? dS : cprev1;
            sum_r1 = fmaf(fr, vr, sum_r1);
            sum_i1 = fmaf(fi, vi, sum_i1);
        }

        up0 = u0; hp0 = hc0; sprev0 = s0; cprev0 = c0;
        up1 = u1; hp1 = hc1; sprev1 = s1; cprev1 = c1;
    }

    float* out_r = out + (b * 2 + 0) * N;
    float* out_i = out + (b * 2 + 1) * N;
    out_r[n0] = scale0 * sum_r0;
    out_i[n0] = scale0 * sum_i0;
    out_r[n1] = scale1 * sum_r1;
    out_i[n1] = scale1 * sum_i1;
}

extern "C" void kernel_launch(void* const* d_in, const int* in_sizes, int n_in,
                              void* d_out, int out_size) {
    const float* points = (const float*)d_in[0];  // [B, 64, 2] f32
    const float* phi    = (const float*)d_in[1];  // [N] f32
    float* out = (float*)d_out;                   // [B, 2, N] f32

    const int N = in_sizes[1];
    const int B = in_sizes[0] / (2 * NPTS);
    const int half = N >> 1;

    dim3 grid((half + BDIM - 1) / BDIM, B);
    scatter_polygon_kernel<<<grid, BDIM>>>(points, phi, out, B, N);
}